// round 15
// baseline (speedup 1.0000x reference)
#include <cuda_runtime.h>
#include <cstdint>
#include <math.h>

// Problem constants (fixed by the reference)
#define NUM_K    1024      // primitives / codebook size
#define NUM_ROWS 32768     // 8 * 4096 tokens
#define DIM_D    1024      // embedding dim

#define TINY_F   1.17549435e-38f
#define LN2_F    0.693147180559945f
// clamp floor in w-space: w = lg2(u) (<=0); w > -W_SMALL <=> t < 4e-3 (forced band)
#define W_SMALL  5.770780e-3f
#define U_FORCE  0.99599f  // u > U_FORCE covers the clamped band with margin
#define CAND_EPS 3e-4f     // >3x proven |za' - (z_exact - C)| bound for unclamped elems
#define NEG_INF  __int_as_float(0xff800000)

// add via IMAD on the fma pipe (one==1 is an opaque kernel arg)
__device__ __forceinline__ uint32_t addf(uint32_t a, uint32_t b, uint32_t one) {
    uint32_t r;
    asm("mad.lo.u32 %0, %1, %2, %3;" : "=r"(r) : "r"(a), "r"(one), "r"(b));
    return r;
}

// bits>>9 as hi32(bits * 2^23) on the fma pipe (IMAD.WIDE)
__device__ __forceinline__ uint32_t shr9_fma(uint32_t bits) {
    uint64_t p;
    asm("mul.wide.u32 %0, %1, %2;" : "=l"(p) : "r"(bits), "r"(1u << 23));
    return (uint32_t)(p >> 32);
}

// order-preserving float->uint map (IEEE total order for non-NaN)
__device__ __forceinline__ uint32_t f2ord(float f) {
    uint32_t b = __float_as_uint(f);
    return b ^ ((uint32_t)((int)b >> 31) | 0x80000000u);
}
__device__ __forceinline__ float ord2f(uint32_t k) {
    uint32_t b = k ^ ((uint32_t)((int)(~k) >> 31) | 0x80000000u);
    return __uint_as_float(b);
}

__device__ __forceinline__ uint32_t redux_max_u32(uint32_t v) {
    uint32_t r;
    asm("redux.sync.max.u32 %0, %1, 0xffffffff;" : "=r"(r) : "r"(v));
    return r;
}
__device__ __forceinline__ int redux_min_s32(int v) {
    int r;
    asm("redux.sync.min.s32 %0, %1, 0xffffffff;" : "=r"(r) : "r"(v));
    return r;
}

// ---------------------------------------------------------------------------
// Threefry-2x32, 20 rounds, key = (0, 42). counter=(0, elem); out = x0^x1.
// SHF rotates (alu, locked); adds on IMAD (fma pipe); counter add folded into
// the first key injection; round-1 "x0 += x1" peepholed (x0 starts at 0).
// ---------------------------------------------------------------------------
__device__ __forceinline__ uint32_t tf_rotl(uint32_t x, int r) {
    return (x << r) | (x >> (32 - r));
}

__device__ __forceinline__ uint32_t threefry_xor(uint32_t base, uint32_t k42i, uint32_t one) {
    const uint32_t ks1 = 42u;
    const uint32_t ks2 = 0x1BD11BDAu ^ 42u;
    uint32_t x1 = addf(base, k42i, one);
    uint32_t x0 = x1;                      // round-1 add with x0==0 peepholed
    x1 = tf_rotl(x1, 13) ^ x0;
#define TF_R(r) { x0 = addf(x1, x0, one); x1 = tf_rotl(x1, (r)); x1 ^= x0; }
    TF_R(15) TF_R(26) TF_R(6)
    x0 = addf(x0, ks1, one);      x1 = addf(x1, ks2 + 1u, one);
    TF_R(17) TF_R(29) TF_R(16) TF_R(24)
    x0 = addf(x0, ks2, one);      x1 = addf(x1, 0u + 2u, one);
    TF_R(13) TF_R(15) TF_R(26) TF_R(6)
    x0 = addf(x0, 0u, one);       x1 = addf(x1, ks1 + 3u, one);
    TF_R(17) TF_R(29) TF_R(16) TF_R(24)
    x0 = addf(x0, ks1, one);      x1 = addf(x1, ks2 + 4u, one);
    TF_R(13) TF_R(15) TF_R(26) TF_R(6)
    x0 = addf(x0, ks2, one);      x1 = addf(x1, 0u + 5u, one);
#undef TF_R
    return x0 ^ x1;
}

// Exact gumbel: identical formula/precision to the reference. Clamp here.
__device__ __forceinline__ float gumbel_exact(float f) {
    float u = fmaxf(f, TINY_F);
    return -logf(-logf(u));
}

__global__ void vybn_zero_counts(float* __restrict__ out, long long out_elems) {
    int k = threadIdx.x;
    long long off = (long long)NUM_ROWS * DIM_D + NUM_ROWS + k;
    if (off < out_elems) out[off] = 0.0f;
}

// ---------------------------------------------------------------------------
// One block (128 threads) per row; 8 elements/thread.
// Live state minimized: ONLY u[8] survives phase 1 (za recomputed and logits
// reloaded via __ldg inside the rare phase-2 path) -> fewer registers ->
// higher occupancy -> more latency hiding for the issue-bound stream.
// Phase 1: za' = fma(lg2(-fmin(lg2(u), -W_SMALL)), -ln2, logit); track zmax,
//   umax. Clamped band -> lower bound -> gmax never inflated -> screen sound.
// Phase 2 (guard = OR of per-elem candidacy): recompute za bit-identically,
//   test, exact logf for candidates; min-index tie-break.
// ---------------------------------------------------------------------------
__global__ __launch_bounds__(128)
void vybn_fused_kernel(const float* __restrict__ logits,
                       const float* __restrict__ prim,
                       float* __restrict__ out,
                       long long out_elems,
                       uint32_t one) {
    const int row  = blockIdx.x;
    const int t    = threadIdx.x;
    const int lane = t & 31;
    const int warp = t >> 5;

    const float4 lv0 = ((const float4*)(logits + (size_t)row * NUM_K))[t];
    const float4 lv1 = ((const float4*)(logits + (size_t)row * NUM_K))[t + 128];
    const float lvi[8] = {lv0.x, lv0.y, lv0.z, lv0.w, lv1.x, lv1.y, lv1.z, lv1.w};
    const uint32_t baseA = (uint32_t)row * (uint32_t)NUM_K + (uint32_t)(4 * t);

    float u[8];   // raw uniform (unclamped) — the ONLY per-elem state kept
    float zmax = NEG_INF;
    float umax = NEG_INF;

    #pragma unroll
    for (int i = 0; i < 8; i++) {
        const uint32_t koff = (i < 4) ? (uint32_t)i : (512u + (uint32_t)(i - 4));
        uint32_t bits = threefry_xor(baseA, 42u + koff, one);
        uint32_t mant = shr9_fma(bits);
        float f = __uint_as_float(addf(mant, 0x3f800000u, one)) - 1.0f;
        u[i] = f;
        umax = fmaxf(umax, f);
        float w  = __log2f(f);               // <= 0; MUFU.LG2
        float wc = fminf(w, -W_SMALL);       // clamp (forced band -> lower bound)
        float za = fmaf(__log2f(-wc), -LN2_F, lvi[i]);
        zmax = fmaxf(zmax, za);
    }

    // warp max of za' via single redux on order-mapped bits
    uint32_t word = redux_max_u32(f2ord(zmax));

    __shared__ uint32_t swv[4];
    __shared__ uint32_t swe[4];
    __shared__ int      swi[4];
    __shared__ int      s_idx;
    if (lane == 0) swv[warp] = word;
    __syncthreads();

    uint32_t gord = max(max(swv[0], swv[1]), max(swv[2], swv[3]));
    const float thresh = ord2f(gord) - CAND_EPS;

    // Phase 2: thread guard == OR of per-element candidacy; za recomputed
    // bit-identically; logit reloaded via __ldg (L1-hot, rare threads only)
    float best = NEG_INF;
    int   bidx = 0x7FFFFFFF;
    if ((zmax >= thresh) || (umax > U_FORCE)) {
        #pragma unroll
        for (int i = 0; i < 8; i++) {
            const int kidx = (i < 4) ? (4 * t + i) : (512 + 4 * t + (i - 4));
            float l  = __ldg(logits + (size_t)row * NUM_K + kidx);
            float w  = __log2f(u[i]);
            float wc = fminf(w, -W_SMALL);
            float za = fmaf(__log2f(-wc), -LN2_F, l);
            if ((za >= thresh) || (u[i] > U_FORCE)) {
                float ze = l + gumbel_exact(u[i]);
                // index-ascending per thread -> strict > keeps first occurrence
                if (ze > best) { best = ze; bidx = kidx; }
            }
        }
    }

    // warp argmax via redux: max of ord(best), then min index among matchers
    uint32_t bord = f2ord(best);
    uint32_t wmax = redux_max_u32(bord);
    int cidx = (bord == wmax) ? bidx : 0x7FFFFFFF;
    int widx = redux_min_s32(cidx);
    if (lane == 0) { swe[warp] = wmax; swi[warp] = widx; }
    __syncthreads();

    if (t == 0) {
        uint32_t bo = swe[0]; int bi = swi[0];
        #pragma unroll
        for (int w = 1; w < 4; w++) {
            if (swe[w] > bo || (swe[w] == bo && swi[w] < bi)) { bo = swe[w]; bi = swi[w]; }
        }
        s_idx = bi;
        long long coff = (long long)NUM_ROWS * DIM_D + NUM_ROWS + bi;
        if (coff < out_elems) atomicAdd(&out[coff], 1.0f);
        long long ioff = (long long)NUM_ROWS * DIM_D + row;
        if (ioff < out_elems) out[ioff] = (float)bi;
    }
    __syncthreads();

    const int idx = s_idx;
    // embeddings row = primitives[idx] exactly (hard one-hot forward)
    float4 v0 = ((const float4*)(prim + (size_t)idx * DIM_D))[t];
    float4 v1 = ((const float4*)(prim + (size_t)idx * DIM_D))[t + 128];
    ((float4*)(out + (size_t)row * DIM_D))[t]       = v0;
    ((float4*)(out + (size_t)row * DIM_D))[t + 128] = v1;
}

extern "C" void kernel_launch(void* const* d_in, const int* in_sizes, int n_in,
                              void* d_out, int out_size) {
    const float* logits = (const float*)d_in[0];
    const float* prim   = (const float*)d_in[1];
    if (n_in >= 2 && in_sizes[0] < in_sizes[1]) {
        const float* tmp = logits; logits = prim; prim = tmp;
    }
    float* out = (float*)d_out;

    vybn_zero_counts<<<1, NUM_K>>>(out, (long long)out_size);
    vybn_fused_kernel<<<NUM_ROWS, 128>>>(logits, prim, out, (long long)out_size, 1u);
}

// round 16
// speedup vs baseline: 1.0059x; 1.0059x over previous
#include <cuda_runtime.h>
#include <cstdint>
#include <math.h>

// Problem constants (fixed by the reference)
#define NUM_K    1024      // primitives / codebook size
#define NUM_ROWS 32768     // 8 * 4096 tokens
#define DIM_D    1024      // embedding dim

#define TINY_F   1.17549435e-38f
#define LN2_F    0.693147180559945f
// clamp floor in w-space: w = lg2(u) (<=0); w > -W_SMALL <=> t < 4e-3 (forced band)
#define W_SMALL  5.770780e-3f
#define U_FORCE  0.99599f  // u > U_FORCE covers the clamped band with margin
#define CAND_EPS 3e-4f     // >3x proven |za' - (z_exact - C)| bound for unclamped elems
#define NEG_INF  __int_as_float(0xff800000)

// add via IMAD on the fma pipe (one==1 is an opaque kernel arg)
__device__ __forceinline__ uint32_t addf(uint32_t a, uint32_t b, uint32_t one) {
    uint32_t r;
    asm("mad.lo.u32 %0, %1, %2, %3;" : "=r"(r) : "r"(a), "r"(one), "r"(b));
    return r;
}

// bits>>9 as hi32(bits * 2^23) on the fma pipe (IMAD.WIDE)
__device__ __forceinline__ uint32_t shr9_fma(uint32_t bits) {
    uint64_t p;
    asm("mul.wide.u32 %0, %1, %2;" : "=l"(p) : "r"(bits), "r"(1u << 23));
    return (uint32_t)(p >> 32);
}

// order-preserving float->uint map (IEEE total order for non-NaN)
__device__ __forceinline__ uint32_t f2ord(float f) {
    uint32_t b = __float_as_uint(f);
    return b ^ ((uint32_t)((int)b >> 31) | 0x80000000u);
}
__device__ __forceinline__ float ord2f(uint32_t k) {
    uint32_t b = k ^ ((uint32_t)((int)(~k) >> 31) | 0x80000000u);
    return __uint_as_float(b);
}

__device__ __forceinline__ uint32_t redux_max_u32(uint32_t v) {
    uint32_t r;
    asm("redux.sync.max.u32 %0, %1, 0xffffffff;" : "=r"(r) : "r"(v));
    return r;
}
__device__ __forceinline__ int redux_min_s32(int v) {
    int r;
    asm("redux.sync.min.s32 %0, %1, 0xffffffff;" : "=r"(r) : "r"(v));
    return r;
}

// ---------------------------------------------------------------------------
// Threefry-2x32, 20 rounds, key = (0, 42). counter=(0, elem); out = x0^x1.
// SHF rotates (alu, locked); adds on IMAD (fma pipe); counter add folded into
// the first key injection; round-1 "x0 += x1" peepholed (x0 starts at 0).
// ---------------------------------------------------------------------------
__device__ __forceinline__ uint32_t tf_rotl(uint32_t x, int r) {
    return (x << r) | (x >> (32 - r));
}

__device__ __forceinline__ uint32_t threefry_xor(uint32_t base, uint32_t k42i, uint32_t one) {
    const uint32_t ks1 = 42u;
    const uint32_t ks2 = 0x1BD11BDAu ^ 42u;
    uint32_t x1 = addf(base, k42i, one);
    uint32_t x0 = x1;                      // round-1 add with x0==0 peepholed
    x1 = tf_rotl(x1, 13) ^ x0;
#define TF_R(r) { x0 = addf(x1, x0, one); x1 = tf_rotl(x1, (r)); x1 ^= x0; }
    TF_R(15) TF_R(26) TF_R(6)
    x0 = addf(x0, ks1, one);      x1 = addf(x1, ks2 + 1u, one);
    TF_R(17) TF_R(29) TF_R(16) TF_R(24)
    x0 = addf(x0, ks2, one);      x1 = addf(x1, 0u + 2u, one);
    TF_R(13) TF_R(15) TF_R(26) TF_R(6)
    x0 = addf(x0, 0u, one);       x1 = addf(x1, ks1 + 3u, one);
    TF_R(17) TF_R(29) TF_R(16) TF_R(24)
    x0 = addf(x0, ks1, one);      x1 = addf(x1, ks2 + 4u, one);
    TF_R(13) TF_R(15) TF_R(26) TF_R(6)
    x0 = addf(x0, ks2, one);      x1 = addf(x1, 0u + 5u, one);
#undef TF_R
    return x0 ^ x1;
}

// Exact gumbel: identical formula/precision to the reference. Clamp here.
__device__ __forceinline__ float gumbel_exact(float f) {
    float u = fmaxf(f, TINY_F);
    return -logf(-logf(u));
}

__global__ void vybn_zero_counts(float* __restrict__ out, long long out_elems) {
    int k = threadIdx.x;
    long long off = (long long)NUM_ROWS * DIM_D + NUM_ROWS + k;
    if (off < out_elems) out[off] = 0.0f;
}

// ---------------------------------------------------------------------------
// One block (128 threads) per row; 8 elements/thread. (R14 structure.)
// Phase 1: za' = fma(lg2(-fmin(lg2(u), -W_SMALL)), -ln2, logit); track zmax,
//   umax. Clamped band -> lower bound -> gmax never inflated -> screen sound.
// Phase 2 (thread guard = OR of per-elem candidacy): exact logf for
//   candidates; min-index tie-break; redux argmax.
// Epilogue: only TWO barriers — after the second, EVERY thread computes the
//   block winner from the 4 smem pairs itself (no s_idx broadcast, no third
//   __syncthreads, no t0-serial critical path before the gather).
// ---------------------------------------------------------------------------
__global__ __launch_bounds__(128)
void vybn_fused_kernel(const float* __restrict__ logits,
                       const float* __restrict__ prim,
                       float* __restrict__ out,
                       long long out_elems,
                       uint32_t one) {
    const int row  = blockIdx.x;
    const int t    = threadIdx.x;
    const int lane = t & 31;
    const int warp = t >> 5;

    const float4 lv0 = ((const float4*)(logits + (size_t)row * NUM_K))[t];
    const float4 lv1 = ((const float4*)(logits + (size_t)row * NUM_K))[t + 128];
    const float lvi[8] = {lv0.x, lv0.y, lv0.z, lv0.w, lv1.x, lv1.y, lv1.z, lv1.w};
    const uint32_t baseA = (uint32_t)row * (uint32_t)NUM_K + (uint32_t)(4 * t);

    float u[8];   // raw uniform (unclamped), kept for the exact rescue path
    float za[8];  // z approx minus constant (lower bound in the clamped region)
    float zmax = NEG_INF;
    float umax = NEG_INF;

    #pragma unroll
    for (int i = 0; i < 8; i++) {
        const uint32_t koff = (i < 4) ? (uint32_t)i : (512u + (uint32_t)(i - 4));
        uint32_t bits = threefry_xor(baseA, 42u + koff, one);
        uint32_t mant = shr9_fma(bits);
        float f = __uint_as_float(addf(mant, 0x3f800000u, one)) - 1.0f;
        u[i] = f;
        umax = fmaxf(umax, f);
        float w  = __log2f(f);               // <= 0; MUFU.LG2
        float wc = fminf(w, -W_SMALL);       // clamp (forced band -> lower bound)
        za[i] = fmaf(__log2f(-wc), -LN2_F, lvi[i]);
        zmax = fmaxf(zmax, za[i]);
    }

    // warp max of za' via single redux on order-mapped bits
    uint32_t word = redux_max_u32(f2ord(zmax));

    __shared__ uint32_t swv[4];
    __shared__ uint32_t swe[4];
    __shared__ int      swi[4];
    if (lane == 0) swv[warp] = word;
    __syncthreads();

    uint32_t gord = max(max(swv[0], swv[1]), max(swv[2], swv[3]));
    const float thresh = ord2f(gord) - CAND_EPS;

    // Phase 2: thread-level guard == OR of per-element candidacy conditions
    float best = NEG_INF;
    int   bidx = 0x7FFFFFFF;
    if ((zmax >= thresh) || (umax > U_FORCE)) {
        #pragma unroll
        for (int i = 0; i < 8; i++) {
            if ((za[i] >= thresh) || (u[i] > U_FORCE)) {
                const int kidx = (i < 4) ? (4 * t + i) : (512 + 4 * t + (i - 4));
                float ze = lvi[i] + gumbel_exact(u[i]);
                // index-ascending per thread -> strict > keeps first occurrence
                if (ze > best) { best = ze; bidx = kidx; }
            }
        }
    }

    // warp argmax via redux: max of ord(best), then min index among matchers
    uint32_t bord = f2ord(best);
    uint32_t wmax = redux_max_u32(bord);
    int cidx = (bord == wmax) ? bidx : 0x7FFFFFFF;
    int widx = redux_min_s32(cidx);
    if (lane == 0) { swe[warp] = wmax; swi[warp] = widx; }
    __syncthreads();

    // EVERY thread computes the block winner (identical result; no broadcast,
    // no third barrier, no serial t0 section on the gather critical path).
    uint32_t bo = swe[0]; int bi = swi[0];
    #pragma unroll
    for (int w = 1; w < 4; w++) {
        if (swe[w] > bo || (swe[w] == bo && swi[w] < bi)) { bo = swe[w]; bi = swi[w]; }
    }

    if (t == 0) {
        // counts: exact order-independent float accumulation (adds of 1.0f)
        long long coff = (long long)NUM_ROWS * DIM_D + NUM_ROWS + bi;
        if (coff < out_elems) atomicAdd(&out[coff], 1.0f);
        long long ioff = (long long)NUM_ROWS * DIM_D + row;
        if (ioff < out_elems) out[ioff] = (float)bi;
    }

    // embeddings row = primitives[bi] exactly (hard one-hot forward)
    float4 v0 = ((const float4*)(prim + (size_t)bi * DIM_D))[t];
    float4 v1 = ((const float4*)(prim + (size_t)bi * DIM_D))[t + 128];
    ((float4*)(out + (size_t)row * DIM_D))[t]       = v0;
    ((float4*)(out + (size_t)row * DIM_D))[t + 128] = v1;
}

extern "C" void kernel_launch(void* const* d_in, const int* in_sizes, int n_in,
                              void* d_out, int out_size) {
    const float* logits = (const float*)d_in[0];
    const float* prim   = (const float*)d_in[1];
    if (n_in >= 2 && in_sizes[0] < in_sizes[1]) {
        const float* tmp = logits; logits = prim; prim = tmp;
    }
    float* out = (float*)d_out;

    vybn_zero_counts<<<1, NUM_K>>>(out, (long long)out_size);
    vybn_fused_kernel<<<NUM_ROWS, 128>>>(logits, prim, out, (long long)out_size, 1u);
}